// round 4
// baseline (speedup 1.0000x reference)
#include <cuda_runtime.h>

// Fixed problem shape.
#define BB 8
#define QQ 900
#define KK 1203
#define NN 100
#define RPB 8            // rows (q values) per block, one per warp
#define THREADS 256

// cost[b,q,n] = 2*focal_cls(gathered logit) + 5*L1(box) - 2*GIoU(box)
// Strategy: stream full logits rows into SMEM coalesced (float4), select by
// label via LDS. Converts random 32B-sector DRAM gathers into sequential
// streaming reads.
__global__ void __launch_bounds__(THREADS) matcher_cost_kernel(
    const float*  __restrict__ logits,   // (B,Q,K)
    const float4* __restrict__ pboxes,   // (B,Q,4)
    const int*    __restrict__ labels,   // (B,N) int32
    const float4* __restrict__ tboxes,   // (B,N,4)
    float* __restrict__ out)             // (B,Q,N)
{
    __shared__ float  s_rows[RPB][KK];   // 38,496 B
    __shared__ float4 s_tb[NN];          // target boxes cxcywh
    __shared__ float4 s_txy[NN];         // target boxes xyxy
    __shared__ float  s_ta[NN];          // target areas
    __shared__ int    s_lab[NN];         // clamped labels

    const int b   = blockIdx.y;
    const int q0  = blockIdx.x * RPB;
    const int tid = threadIdx.x;
    const int w    = tid >> 5;
    const int lane = tid & 31;

    // ---- stage per-batch target data (once per block) ----
    if (tid < NN) {
        int l = labels[b * NN + tid];
        s_lab[tid] = min(max(l, 0), KK - 1);
        float4 tb = tboxes[b * NN + tid];
        s_tb[tid] = tb;
        float4 xy;
        xy.x = tb.x - 0.5f * tb.z;   // tx0
        xy.y = tb.y - 0.5f * tb.w;   // ty0
        xy.z = tb.x + 0.5f * tb.z;   // tx1
        xy.w = tb.y + 0.5f * tb.w;   // ty1
        s_txy[tid] = xy;
        s_ta[tid]  = tb.z * tb.w;
    }

    // ---- stage logits row: warp w streams row q0+w, coalesced float4 ----
    const int q = q0 + w;
    if (q < QQ) {
        const long E = (long)(b * QQ + q) * KK;      // element offset of row
        const float* src = logits + E;
        float* dst = s_rows[w];
        const int head = (4 - ((int)E & 3)) & 3;      // floats until 16B-aligned
        if (lane < head) dst[lane] = src[lane];
        const float4* vsrc = (const float4*)(src + head);
        // (KK - head) >> 2 == 300 for all head in 0..3
        #pragma unroll
        for (int i = 0; i < 10; i++) {
            int idx = lane + i * 32;
            if (idx < 300) {
                float4 v = vsrc[idx];
                int o = head + idx * 4;
                dst[o]     = v.x;
                dst[o + 1] = v.y;
                dst[o + 2] = v.z;
                dst[o + 3] = v.w;
            }
        }
        const int done = head + 1200;
        if (lane < KK - done) dst[done + lane] = src[done + lane];
    }
    __syncthreads();

    if (q >= QQ) return;   // ragged last block (no more barriers below)

    // ---- per-row (warp-uniform) precompute ----
    const float4 pb = pboxes[b * QQ + q];
    const float px0 = pb.x - 0.5f * pb.z, px1 = pb.x + 0.5f * pb.z;
    const float py0 = pb.y - 0.5f * pb.w, py1 = pb.y + 0.5f * pb.w;
    const float area1 = pb.z * pb.w;
    float* orow = out + (long)(b * QQ + q) * NN;
    const float* row = s_rows[w];

    // ---- 100 outputs per warp: lane handles n = lane, lane+32, +64, +96 ----
    #pragma unroll
    for (int i = 0; i < 4; i++) {
        int n = lane + i * 32;
        if (n < NN) {
            float x = row[s_lab[n]];          // LDS select (random bank, cheap)

            // focal class cost (3 MUFU)
            // p = sigmoid(x); L = log(1+e^-x) = -log p; log(1-p) = -x - L
            float e  = __expf(-x);
            float s  = 1.0f + e;
            float p  = __fdividef(1.0f, s);
            float L  = __logf(s);
            float logp   = fmaxf(-L,     -18.420681f);
            float log1mp = fmaxf(-x - L, -18.420681f);
            float omp = 1.0f - p;
            float cls = -0.25f * omp * omp * logp + 0.75f * p * p * log1mp;

            // L1 box cost
            float4 tb = s_tb[n];
            float l1 = fabsf(pb.x - tb.x) + fabsf(pb.y - tb.y)
                     + fabsf(pb.z - tb.z) + fabsf(pb.w - tb.w);

            // GIoU (1 MUFU)
            float4 xy = s_txy[n];
            float area2 = s_ta[n];
            float wi = fmaxf(fminf(px1, xy.z) - fmaxf(px0, xy.x), 0.0f);
            float hi = fmaxf(fminf(py1, xy.w) - fmaxf(py0, xy.y), 0.0f);
            float inter = wi * hi;
            float uni   = area1 + area2 - inter;
            float wc = fmaxf(px1, xy.z) - fminf(px0, xy.x);
            float hc = fmaxf(py1, xy.w) - fminf(py0, xy.y);
            float ac = wc * hc;
            // giou = inter/uni - (ac-uni)/ac = (ac*(inter-uni)+uni*uni)/(uni*ac)
            float num  = ac * (inter - uni) + uni * uni;
            float giou = num * __fdividef(1.0f, uni * ac);

            orow[n] = 2.0f * cls + 5.0f * l1 - 2.0f * giou;
        }
    }
}

extern "C" void kernel_launch(void* const* d_in, const int* in_sizes, int n_in,
                              void* d_out, int out_size)
{
    const float*  logits = (const float*)d_in[0];
    const float4* pboxes = (const float4*)d_in[1];
    const int*    labels = (const int*)d_in[2];
    const float4* tboxes = (const float4*)d_in[3];
    float* out = (float*)d_out;

    dim3 grid((QQ + RPB - 1) / RPB, BB);   // (113, 8)
    matcher_cost_kernel<<<grid, THREADS>>>(logits, pboxes, labels, tboxes, out);
}